// round 3
// baseline (speedup 1.0000x reference)
#include <cuda_runtime.h>
#include <cstdint>

// Problem dims
#define B_    32
#define CIN_  32
#define COUT_ 64
#define H_    128
#define W_    128
#define HO_   126
#define WO_   126
#define MAXCN_ 64

// Folded dense kernel: [COUT][CIN][3*3]
__device__ float g_kdense[COUT_ * CIN_ * 9];

__global__ void fold_kernel(const float* __restrict__ w, const int* __restrict__ cn) {
    int idx = blockIdx.x * blockDim.x + threadIdx.x;
    if (idx >= COUT_ * CIN_ * 9) return;
    int k = idx % 9;
    int c = (idx / 9) % CIN_;
    int o = idx / (9 * CIN_);
    int n = cn[o];
    float v = 0.f;
    if (c < n)        v += w[(o * MAXCN_ + c) * 9 + k];
    if (c + 32 < n)   v += w[(o * MAXCN_ + c + 32) * 9 + k];
    g_kdense[idx] = v;
}

// ---- packed f32x2 helpers (sm_103a dual-rate fp32 path; ptxas never emits these) ----
__device__ __forceinline__ unsigned long long pack2(float lo, float hi) {
    unsigned long long r;
    asm("mov.b64 %0, {%1, %2};" : "=l"(r) : "f"(lo), "f"(hi));
    return r;
}
__device__ __forceinline__ unsigned long long fma2(unsigned long long a, unsigned long long b,
                                                   unsigned long long c) {
    unsigned long long d;
    asm("fma.rn.f32x2 %0, %1, %2, %3;" : "=l"(d) : "l"(a), "l"(b), "l"(c));
    return d;
}
__device__ __forceinline__ void unpack2(unsigned long long v, float& lo, float& hi) {
    asm("mov.b64 {%0, %1}, %2;" : "=f"(lo), "=f"(hi) : "l"(v));
}

#define SIN_STRIDE 72   // 10 rows x 72 (66 used); conflict-free for compute reads

// Block: 512 threads = 8 oc-groups x 8 ho x 8 wo-lanes.
// Each thread: 4 oc-PAIRS (f32x2) x 8 output columns (stride 8) x 1 row.
// Tile: all 64 oc x 8 ho x 64 wo for one batch image. Double-buffered smem.
__global__ __launch_bounds__(512, 1)
void conv_kernel(const float* __restrict__ x,
                 const float* __restrict__ bias,
                 float* __restrict__ out) {
    __shared__ float sIn[2][10 * SIN_STRIDE];
    __shared__ float sW[2][COUT_ * 9];

    const int tid  = threadIdx.x;
    const int og   = tid >> 6;          // 0..7  (oc group of 8) — warp-uniform
    const int ho_i = (tid >> 3) & 7;    // 0..7
    const int wo_g = tid & 7;           // 0..7

    const int wo0 = blockIdx.x * 64;    // 0 or 64
    const int ho0 = blockIdx.y * 8;     // 0..120
    const int b   = blockIdx.z;

    // ---- input staging slots (10*66 = 660 elems, <=2 per thread) ----
    const int i0 = tid;
    const int i1 = tid + 512;
    const int r0 = i0 / 66, c0 = i0 % 66;
    const int r1 = i1 / 66, c1 = i1 % 66;
    const int row0 = ho0 + r0, col0 = wo0 + c0;
    const int row1 = ho0 + r1, col1 = wo0 + c1;
    const bool st1 = (i1 < 660);
    const bool v0  = (row0 < H_) && (col0 < W_);
    const bool v1  = st1 && (row1 < H_) && (col1 < W_);
    const int goff0 = row0 * W_ + col0;
    const int goff1 = row1 * W_ + col1;
    const float* xb = x + (long)b * CIN_ * H_ * W_;

    // ---- weight staging slots (64*9 = 576 elems) ----
    const int wi0 = tid;
    const int wi1 = tid + 512;
    const bool wv1 = (wi1 < 576);

    unsigned long long acc2[4][8];
    #pragma unroll
    for (int r = 0; r < 4; ++r)
        #pragma unroll
        for (int j = 0; j < 8; ++j) acc2[r][j] = 0ull;  // (0.0f, 0.0f)

    // prefetch channel 0
    float pi0 = v0 ? __ldg(xb + goff0) : 0.f;
    float pi1 = v1 ? __ldg(xb + goff1) : 0.f;
    float pw0 = g_kdense[(wi0 / 9) * CIN_ * 9 + 0 * 9 + (wi0 % 9)];
    float pw1 = wv1 ? g_kdense[(wi1 / 9) * CIN_ * 9 + 0 * 9 + (wi1 % 9)] : 0.f;

    // stage channel 0 into buffer 0
    sIn[0][r0 * SIN_STRIDE + c0] = pi0;
    if (st1) sIn[0][r1 * SIN_STRIDE + c1] = pi1;
    sW[0][wi0] = pw0;
    if (wv1) sW[0][wi1] = pw1;
    __syncthreads();

    for (int c = 0; c < CIN_; ++c) {
        const int cur = c & 1;

        // prefetch next channel into registers (latency hidden by compute below)
        if (c < CIN_ - 1) {
            const float* xc = xb + (long)(c + 1) * (H_ * W_);
            pi0 = v0 ? __ldg(xc + goff0) : 0.f;
            pi1 = v1 ? __ldg(xc + goff1) : 0.f;
            pw0 = g_kdense[(wi0 / 9) * CIN_ * 9 + (c + 1) * 9 + (wi0 % 9)];
            if (wv1) pw1 = g_kdense[(wi1 / 9) * CIN_ * 9 + (c + 1) * 9 + (wi1 % 9)];
        }

        // compute on buf[cur]: per thread 288 FMA2 per channel
        #pragma unroll
        for (int kh = 0; kh < 3; ++kh) {
            const float* rowp = &sIn[cur][(ho_i + kh) * SIN_STRIDE + wo_g];
            const float* wbase = &sW[cur][(og * 8) * 9 + kh * 3];
            // weight pairs: (oc=2r, oc=2r+1) per kw — 12 pairs, warp-broadcast LDS
            unsigned long long wp[4][3];
            #pragma unroll
            for (int r = 0; r < 4; ++r)
                #pragma unroll
                for (int kw = 0; kw < 3; ++kw)
                    wp[r][kw] = pack2(wbase[(2 * r) * 9 + kw], wbase[(2 * r + 1) * 9 + kw]);

            #pragma unroll
            for (int j = 0; j < 8; ++j) {
                float a0 = rowp[8 * j];
                float a1 = rowp[8 * j + 1];
                float a2 = rowp[8 * j + 2];
                unsigned long long a0d = pack2(a0, a0);
                unsigned long long a1d = pack2(a1, a1);
                unsigned long long a2d = pack2(a2, a2);
                #pragma unroll
                for (int r = 0; r < 4; ++r) {
                    unsigned long long t = acc2[r][j];
                    t = fma2(wp[r][0], a0d, t);
                    t = fma2(wp[r][1], a1d, t);
                    t = fma2(wp[r][2], a2d, t);
                    acc2[r][j] = t;
                }
            }
        }

        // stage next channel into the other buffer, one barrier per iteration
        if (c < CIN_ - 1) {
            const int nxt = cur ^ 1;
            sIn[nxt][r0 * SIN_STRIDE + c0] = pi0;
            if (st1) sIn[nxt][r1 * SIN_STRIDE + c1] = pi1;
            sW[nxt][wi0] = pw0;
            if (wv1) sW[nxt][wi1] = pw1;
            __syncthreads();
        }
    }

    // epilogue: add bias, store (coalesced: lanes wo_g consecutive columns)
    const int ho = ho0 + ho_i;
    if (ho < HO_) {
        #pragma unroll
        for (int r = 0; r < 4; ++r) {
            const int ocA = og * 8 + 2 * r;
            const int ocB = ocA + 1;
            const float* bpA = bias + ((long)ocA * HO_ + ho) * WO_;
            const float* bpB = bias + ((long)ocB * HO_ + ho) * WO_;
            float* opA = out + (((long)b * COUT_ + ocA) * HO_ + ho) * WO_;
            float* opB = out + (((long)b * COUT_ + ocB) * HO_ + ho) * WO_;
            #pragma unroll
            for (int j = 0; j < 8; ++j) {
                const int wo = wo0 + wo_g + 8 * j;
                if (wo < WO_) {
                    float lo, hi;
                    unpack2(acc2[r][j], lo, hi);
                    opA[wo] = lo + __ldg(bpA + wo);
                    opB[wo] = hi + __ldg(bpB + wo);
                }
            }
        }
    }
}

extern "C" void kernel_launch(void* const* d_in, const int* in_sizes, int n_in,
                              void* d_out, int out_size) {
    const float* x    = (const float*)d_in[0];   // [32,32,128,128]
    const float* w    = (const float*)d_in[1];   // [64,64,3,3]
    const float* bias = (const float*)d_in[2];   // [64,126,126]
    const int*   cn   = (const int*)d_in[3];     // [64]
    float* out = (float*)d_out;                  // [32,64,126,126]

    fold_kernel<<<(COUT_ * CIN_ * 9 + 255) / 256, 256>>>(w, cn);
    conv_kernel<<<dim3(2, 16, 32), 512>>>(x, bias, out);
}

// round 5
// speedup vs baseline: 1.2437x; 1.2437x over previous
#include <cuda_runtime.h>
#include <cuda_bf16.h>
#include <cstdint>

#define B_    32
#define CIN_  32
#define COUT_ 64
#define H_    128
#define W_    128
#define HO_   126
#define WO_   126
#define MAXCN_ 64
#define TILES 14           // output rows per CTA strip; 9 strips x 14 = 126

__device__ float g_kdense[COUT_ * CIN_ * 9];

__global__ void fold_kernel(const float* __restrict__ w, const int* __restrict__ cn) {
    int idx = blockIdx.x * blockDim.x + threadIdx.x;
    if (idx >= COUT_ * CIN_ * 9) return;
    int k = idx % 9;
    int c = (idx / 9) % CIN_;
    int o = idx / (9 * CIN_);
    int n = cn[o];
    float v = 0.f;
    if (c < n)      v += w[(o * MAXCN_ + c) * 9 + k];
    if (c + 32 < n) v += w[(o * MAXCN_ + c + 32) * 9 + k];
    g_kdense[idx] = v;
}

// ---------------- smem layout (bytes) ----------------
// W:  [kw][hl][oc 64][k 96 pad->104] stride 208  -> 6 * 13312
// X:  ring[4][hl][px 130][c 32 pad->40] stride 80 -> 8 * 10400
// E:  transpose buffer [oc 64][wo pad 129 words]  -> 33024
#define WSTRIDE 208
#define WSIZE   13312
#define OFF_W   0
#define XSTRIDE 80
#define XSIZE   10400
#define OFF_X   79872       // 6*13312
#define OFF_E   163072      // OFF_X + 8*10400
#define SMEM_TOTAL 196096   // OFF_E + 64*129*4

__device__ __forceinline__ uint32_t smem_u32(const void* p) {
    uint32_t a;
    asm("{ .reg .u64 t; cvta.to.shared.u64 t, %1; cvt.u32.u64 %0, t; }" : "=r"(a) : "l"(p));
    return a;
}

__device__ __forceinline__ void ldsm4(uint32_t (&r)[4], uint32_t addr) {
    asm volatile("ldmatrix.sync.aligned.m8n8.x4.shared.b16 {%0,%1,%2,%3}, [%4];"
                 : "=r"(r[0]), "=r"(r[1]), "=r"(r[2]), "=r"(r[3]) : "r"(addr));
}

__device__ __forceinline__ void mma16816(float (&d)[4], const uint32_t (&a)[4],
                                         uint32_t b0, uint32_t b1) {
    asm volatile("mma.sync.aligned.m16n8k16.row.col.f32.bf16.bf16.f32 "
                 "{%0,%1,%2,%3}, {%4,%5,%6,%7}, {%8,%9}, {%0,%1,%2,%3};"
                 : "+f"(d[0]), "+f"(d[1]), "+f"(d[2]), "+f"(d[3])
                 : "r"(a[0]), "r"(a[1]), "r"(a[2]), "r"(a[3]), "r"(b0), "r"(b1));
}

__device__ __forceinline__ void cvt_split(float v, __nv_bfloat16& hi, __nv_bfloat16& lo) {
    hi = __float2bfloat16(v);
    lo = __float2bfloat16(v - __bfloat162float(hi));
}

// stage input row ir (32 c x 128 px, hi/lo) into ring slot ir&3, layout [px][c]
__device__ __forceinline__ void stage(char* smem, const float* xb, int ir, int tid) {
    char* hbase = smem + OFF_X + (size_t)((ir & 3) * 2) * XSIZE;
    for (int i = tid; i < CIN_ * W_; i += 256) {
        int c = i >> 7, px = i & 127;                 // lanes = consecutive px -> coalesced LDG
        float v = __ldg(xb + ((long)c * H_ + ir) * W_ + px);
        __nv_bfloat16 hi, lo;
        cvt_split(v, hi, lo);
        *(__nv_bfloat16*)(hbase + px * XSTRIDE + c * 2) = hi;
        *(__nv_bfloat16*)(hbase + XSIZE + px * XSTRIDE + c * 2) = lo;
    }
}

__global__ __launch_bounds__(256, 1)
void conv_kernel(const float* __restrict__ x,
                 const float* __restrict__ bias,
                 float* __restrict__ out) {
    extern __shared__ __align__(128) char smem[];
    const uint32_t sb  = smem_u32(smem);
    const int tid  = threadIdx.x;
    const int lane = tid & 31;
    const int w    = tid >> 5;
    const int b    = blockIdx.x;
    const int r0   = blockIdx.y * TILES;
    const float* xb = x + (long)b * CIN_ * H_ * W_;

    // zero the pad rows 128,129 of every X buffer (read by kw-shift for discarded wo>=126)
    for (int i = tid; i < 8 * 2 * 40; i += 256) {
        int buf = i / 80, rr = (i / 40) & 1, col = i % 40;
        *(uint16_t*)(smem + OFF_X + (size_t)buf * XSIZE + (128 + rr) * XSTRIDE + col * 2) = 0;
    }
    // stage weights: W[kw][hl][oc][k = kh*32 + c]
    for (int i = tid; i < 3 * COUT_ * 96; i += 256) {
        int k = i % 96, oc = (i / 96) & 63, kw = i / (96 * 64);
        int c = k & 31, kh = k >> 5;
        float v = g_kdense[(oc * CIN_ + c) * 9 + kh * 3 + kw];
        __nv_bfloat16 hi, lo;
        cvt_split(v, hi, lo);
        char* base = smem + OFF_W + (size_t)(kw * 2) * WSIZE + oc * WSTRIDE + k * 2;
        *(__nv_bfloat16*)base = hi;
        *(__nv_bfloat16*)(base + WSIZE) = lo;
    }
    stage(smem, xb, r0, tid);
    stage(smem, xb, r0 + 1, tid);

    const int px0 = w * 16;
    // per-lane invariant ldmatrix offsets
    const uint32_t a_lane = (uint32_t)(((lane & 7) + ((lane >> 3) & 1) * 8) * XSTRIDE
                                       + ((lane >> 4) & 1) * 16);
    const uint32_t b_lane = (uint32_t)(((lane & 7) + ((lane >> 4) & 1) * 8) * WSTRIDE
                                       + ((lane >> 3) & 1) * 16);

    for (int pl = 0; pl < TILES / 2; ++pl) {
        const int rg = r0 + 2 * pl;
        stage(smem, xb, rg + 2, tid);
        stage(smem, xb, rg + 3, tid);
        __syncthreads();

        float acc[2][8][4];
        #pragma unroll
        for (int rr = 0; rr < 2; ++rr)
            #pragma unroll
            for (int nt = 0; nt < 8; ++nt)
                #pragma unroll
                for (int j = 0; j < 4; ++j) acc[rr][nt][j] = 0.f;

        #pragma unroll
        for (int s = 0; s < 6; ++s) {
            const int kh = s >> 1;
            const uint32_t acoff = (s & 1) * 32;
            const uint32_t bcoff = (s >> 1) * 64 + (s & 1) * 32;
            #pragma unroll
            for (int kw = 0; kw < 3; ++kw) {
                // B (weight) fragments: 8 n-tiles, hi & lo
                uint32_t bh[16], bl[16];
                const uint32_t wbH = sb + OFF_W + (uint32_t)(kw * 2) * WSIZE + bcoff + b_lane;
                #pragma unroll
                for (int t = 0; t < 4; ++t) {
                    uint32_t r4[4];
                    ldsm4(r4, wbH + (uint32_t)(t * 16) * WSTRIDE);
                    bh[4 * t + 0] = r4[0]; bh[4 * t + 1] = r4[1];
                    bh[4 * t + 2] = r4[2]; bh[4 * t + 3] = r4[3];
                }
                #pragma unroll
                for (int t = 0; t < 4; ++t) {
                    uint32_t r4[4];
                    ldsm4(r4, wbH + WSIZE + (uint32_t)(t * 16) * WSTRIDE);
                    bl[4 * t + 0] = r4[0]; bl[4 * t + 1] = r4[1];
                    bl[4 * t + 2] = r4[2]; bl[4 * t + 3] = r4[3];
                }
                #pragma unroll
                for (int rr = 0; rr < 2; ++rr) {
                    const int slot = (rg + rr + kh) & 3;
                    const uint32_t xbase = sb + OFF_X + (uint32_t)(slot * 2) * XSIZE;
                    const uint32_t aaddr = xbase + (uint32_t)(px0 + kw) * XSTRIDE + acoff + a_lane;
                    uint32_t ah[4], al[4];
                    ldsm4(ah, aaddr);
                    ldsm4(al, aaddr + XSIZE);
                    #pragma unroll
                    for (int nt = 0; nt < 8; ++nt) {
                        mma16816(acc[rr][nt], ah, bh[2 * nt], bh[2 * nt + 1]);  // Xh*Wh
                        mma16816(acc[rr][nt], al, bh[2 * nt], bh[2 * nt + 1]);  // Xl*Wh
                        mma16816(acc[rr][nt], ah, bl[2 * nt], bl[2 * nt + 1]);  // Xh*Wl
                    }
                }
            }
        }

        // epilogue: per row, transpose through smem, coalesced bias+store
        #pragma unroll
        for (int rr = 0; rr < 2; ++rr) {
            const int ho = rg + rr;
            #pragma unroll
            for (int nt = 0; nt < 8; ++nt)
                #pragma unroll
                for (int j = 0; j < 4; ++j) {
                    const int oc = nt * 8 + (lane & 3) * 2 + (j & 1);
                    const int wo = px0 + (lane >> 2) + (j >> 1) * 8;
                    *(float*)(smem + OFF_E + (size_t)(oc * 129 + wo) * 4) = acc[rr][nt][j];
                }
            __syncthreads();
            for (int i = 0; i < 32; ++i) {
                const int lin = i * 256 + tid;
                const int oc = lin >> 7, wo = lin & 127;
                if (wo < WO_) {
                    float v = *(float*)(smem + OFF_E + (size_t)(oc * 129 + wo) * 4)
                            + __ldg(bias + ((long)oc * HO_ + ho) * WO_ + wo);
                    out[(((long)b * COUT_ + oc) * HO_ + ho) * WO_ + wo] = v;
                }
            }
            __syncthreads();
        }
    }
}

extern "C" void kernel_launch(void* const* d_in, const int* in_sizes, int n_in,
                              void* d_out, int out_size) {
    const float* x    = (const float*)d_in[0];   // [32,32,128,128]
    const float* w    = (const float*)d_in[1];   // [64,64,3,3]
    const float* bias = (const float*)d_in[2];   // [64,126,126]
    const int*   cn   = (const int*)d_in[3];     // [64]
    float* out = (float*)d_out;                  // [32,64,126,126]

    fold_kernel<<<(COUT_ * CIN_ * 9 + 255) / 256, 256>>>(w, cn);
    cudaFuncSetAttribute(conv_kernel, cudaFuncAttributeMaxDynamicSharedMemorySize, SMEM_TOTAL);
    conv_kernel<<<dim3(B_, 9), 256, SMEM_TOTAL>>>(x, bias, out);
}